// round 1
// baseline (speedup 1.0000x reference)
#include <cuda_runtime.h>

#define FULL 0xFFFFFFFFu

static constexpr float R2    = 0.03f * 0.03f;   // 9e-4
static constexpr float SIM_T = 0.7f;
static constexpr float EPS   = 1e-8f;

// scratch (no allocations allowed) — sized for B*N = 12288, padded
__device__ float g_enorm[32768];
__device__ int   g_leafsum[8];

// ---------------------------------------------------------------------------
// Prep: per-point embedding norm (warp per point; D == 32 == warp width)
// ---------------------------------------------------------------------------
__global__ void prep_norm_kernel(const float* __restrict__ E, int BN) {
    int wid  = (blockIdx.x * blockDim.x + threadIdx.x) >> 5;
    int lane = threadIdx.x & 31;
    if (wid >= BN) return;
    float v = E[(size_t)wid * 32 + lane];
    float s = v * v;
    #pragma unroll
    for (int o = 16; o; o >>= 1) s += __shfl_xor_sync(FULL, s, o);
    if (lane == 0) g_enorm[wid] = fmaxf(sqrtf(s), EPS);
}

// ---------------------------------------------------------------------------
// Prep: per-batch leaf sum (one block per batch)
// ---------------------------------------------------------------------------
__global__ void leafsum_kernel(const int* __restrict__ leaf, int N) {
    __shared__ int sh[256];
    int b = blockIdx.x;
    int s = 0;
    for (int j = threadIdx.x; j < N; j += blockDim.x) s += leaf[b * N + j];
    sh[threadIdx.x] = s;
    __syncthreads();
    for (int o = 128; o; o >>= 1) {
        if (threadIdx.x < o) sh[threadIdx.x] += sh[threadIdx.x + o];
        __syncthreads();
    }
    if (threadIdx.x == 0) g_leafsum[b] = sh[0];
}

// ---------------------------------------------------------------------------
// Main: warp-per-point neighbor scan + warp MLP
// ---------------------------------------------------------------------------
template <int TJ>
__global__ void __launch_bounds__(256)
main_kernel(const float* __restrict__ P, const float* __restrict__ E,
            const int* __restrict__ leaf,
            const float* __restrict__ W1, const float* __restrict__ b1,
            const float* __restrict__ W2, const float* __restrict__ b2,
            float* __restrict__ out, int N) {
    __shared__ float4 tile[TJ];          // {x, y, z, leaf ? enorm : -1}
    __shared__ float  sW1[64 * 32];
    __shared__ float  sW2[32 * 32];
    __shared__ float  sb1[32], sb2[32];

    const int lane     = threadIdx.x & 31;
    const int warp     = threadIdx.x >> 5;
    const int i_global = blockIdx.x * 8 + warp;   // [0, B*N)
    const int b        = i_global / N;
    const int i        = i_global - b * N;
    (void)i;

    // stage weights
    for (int t = threadIdx.x; t < 64 * 32; t += blockDim.x) sW1[t] = W1[t];
    for (int t = threadIdx.x; t < 32 * 32; t += blockDim.x) sW2[t] = W2[t];
    if (threadIdx.x < 32) { sb1[threadIdx.x] = b1[threadIdx.x]; sb2[threadIdx.x] = b2[threadIdx.x]; }

    const float ei      = E[(size_t)i_global * 32 + lane];
    const bool  leaf_i  = leaf[i_global] > 0;
    const bool  batch_ok = g_leafsum[b] >= 10;
    const bool  active  = leaf_i && batch_ok;

    const float px = P[i_global * 3 + 0];
    const float py = P[i_global * 3 + 1];
    const float pz = P[i_global * 3 + 2];
    const float pni = px * px + py * py + pz * pz;
    const float eni = g_enorm[i_global];

    int   cnt_nb = 0, cnt_sim = 0;
    float ssum = 0.0f;

    const float* Pb  = P + (size_t)b * N * 3;
    const float* Eb  = E + (size_t)b * N * 32;
    const int*   Lb  = leaf + (size_t)b * N;
    const float* ENb = g_enorm + (size_t)b * N;

    const int anyActive = __syncthreads_or(active ? 1 : 0);

    if (anyActive) {
        for (int t0 = 0; t0 < N; t0 += TJ) {
            __syncthreads();
            for (int t = threadIdx.x; t < TJ; t += blockDim.x) {
                int j = t0 + t;
                float4 v;
                v.x = Pb[j * 3 + 0];
                v.y = Pb[j * 3 + 1];
                v.z = Pb[j * 3 + 2];
                v.w = (Lb[j] > 0) ? ENb[j] : -1.0f;
                tile[t] = v;
            }
            __syncthreads();

            if (active) {
                #pragma unroll 4
                for (int jj = lane; jj < TJ; jj += 32) {
                    float4 v = tile[jj];
                    float pnj  = v.x * v.x + v.y * v.y + v.z * v.z;
                    float dot3 = px * v.x + py * v.y + pz * v.z;
                    float d2   = pni + pnj - 2.0f * dot3;   // same Gram trick as reference
                    bool cand = (d2 < R2) && (v.w > 0.0f);
                    unsigned m = __ballot_sync(FULL, cand);
                    cnt_nb += __popc(m);
                    while (m) {
                        int src = __ffs(m) - 1;
                        m &= m - 1;
                        int j = t0 + (jj - lane) + src;      // uniform across warp
                        float enj = __shfl_sync(FULL, v.w, src);
                        float ej  = Eb[(size_t)j * 32 + lane];
                        float d   = ei * ej;
                        #pragma unroll
                        for (int o = 16; o; o >>= 1) d += __shfl_xor_sync(FULL, d, o);
                        float sim = d / (eni * enj);
                        if (sim > SIM_T) { cnt_sim++; ssum += ej; }  // uniform decision
                    }
                }
            }
        }
    }

    float outv = ei;
    if (active && cnt_nb > 1 && cnt_sim > 0) {      // uniform across warp
        float mean = ssum / (float)cnt_sim;
        // h = relu(W1^T * [ei, mean] + b1); combined[k]: k<32 -> ei lanes, k>=32 -> mean lanes
        float h = sb1[lane];
        #pragma unroll
        for (int k = 0; k < 32; k++) {
            float c = __shfl_sync(FULL, ei, k);
            h = fmaf(c, sW1[k * 32 + lane], h);
        }
        #pragma unroll
        for (int k = 0; k < 32; k++) {
            float c = __shfl_sync(FULL, mean, k);
            h = fmaf(c, sW1[(k + 32) * 32 + lane], h);
        }
        h = fmaxf(h, 0.0f);
        float o = sb2[lane];
        #pragma unroll
        for (int k = 0; k < 32; k++) {
            float hk = __shfl_sync(FULL, h, k);
            o = fmaf(hk, sW2[k * 32 + lane], o);
        }
        outv = o;
    }
    out[(size_t)i_global * 32 + lane] = outv;
}

// ---------------------------------------------------------------------------
extern "C" void kernel_launch(void* const* d_in, const int* in_sizes, int n_in,
                              void* d_out, int out_size) {
    const float* P  = (const float*)d_in[0];
    const float* E  = (const float*)d_in[1];
    const int*   L  = (const int*)d_in[2];
    const float* W1 = (const float*)d_in[3];
    const float* b1 = (const float*)d_in[4];
    const float* W2 = (const float*)d_in[5];
    const float* b2 = (const float*)d_in[6];
    float* out = (float*)d_out;

    const int BN = in_sizes[2];   // B*N
    const int B  = 2;
    const int N  = BN / B;

    prep_norm_kernel<<<(BN + 3) / 4, 128>>>(E, BN);
    leafsum_kernel<<<B, 256>>>(L, N);
    main_kernel<1024><<<(BN + 7) / 8, 256>>>(P, E, L, W1, b1, W2, b2, out, N);
}

// round 2
// speedup vs baseline: 2.5718x; 2.5718x over previous
#include <cuda_runtime.h>

#define FULL 0xFFFFFFFFu

static constexpr float R2       = 0.03f * 0.03f;   // 9e-4
static constexpr float SIM_T    = 0.7f;
static constexpr float EPS      = 1e-8f;
static constexpr float INV_CELL = 1.0f / 0.03f;
static constexpr int   GD       = 10;              // cells per dim
static constexpr int   NC       = GD * GD * GD;    // 1000 cells per batch
static constexpr int   HPAD     = 2080;            // >= 2*NC+1, padded

// ---- static scratch (no allocations allowed) ------------------------------
__device__ float4         g_spts[16384];   // sorted: {x,y,z, leaf?enorm:-1}
__device__ int            g_sidx[16384];   // sorted -> original global index
__device__ float          g_enorm[16384];
__device__ unsigned short g_cell[16384];   // global cell id per point
__device__ int            g_hist[HPAD];
__device__ int            g_cellstart[HPAD];
__device__ int            g_cellcur[HPAD];
__device__ int            g_leafsum[8];

// ---------------------------------------------------------------------------
// 0) zero the histograms / leaf sums (graph replays re-run this)
// ---------------------------------------------------------------------------
__global__ void init_kernel() {
    for (int t = threadIdx.x; t < HPAD; t += blockDim.x) g_hist[t] = 0;
    if (threadIdx.x < 8) g_leafsum[threadIdx.x] = 0;
}

// ---------------------------------------------------------------------------
// 1) per-point: embedding norm (warp reduce), cell id, histogram, leaf sums
// ---------------------------------------------------------------------------
__global__ void __launch_bounds__(256)
prep_kernel(const float* __restrict__ P, const float* __restrict__ E,
            const int* __restrict__ leaf, int N, int BN) {
    __shared__ int sl[2];
    if (threadIdx.x < 2) sl[threadIdx.x] = 0;
    __syncthreads();

    int warp = threadIdx.x >> 5, lane = threadIdx.x & 31;
    int gi = blockIdx.x * 8 + warp;
    if (gi < BN) {
        float v = E[(size_t)gi * 32 + lane];
        float s = v * v;
        #pragma unroll
        for (int o = 16; o; o >>= 1) s += __shfl_xor_sync(FULL, s, o);
        if (lane == 0) {
            g_enorm[gi] = fmaxf(sqrtf(s), EPS);
            float x = P[gi * 3 + 0], y = P[gi * 3 + 1], z = P[gi * 3 + 2];
            int cx = min(max((int)(x * INV_CELL), 0), GD - 1);
            int cy = min(max((int)(y * INV_CELL), 0), GD - 1);
            int cz = min(max((int)(z * INV_CELL), 0), GD - 1);
            int b  = gi >= N ? 1 : 0;
            int gc = b * NC + (cz * GD + cy) * GD + cx;
            g_cell[gi] = (unsigned short)gc;
            atomicAdd(&g_hist[gc], 1);
            if (leaf[gi] > 0) atomicAdd(&sl[b], 1);
        }
    }
    __syncthreads();
    if (threadIdx.x < 2 && sl[threadIdx.x]) atomicAdd(&g_leafsum[threadIdx.x], sl[threadIdx.x]);
}

// ---------------------------------------------------------------------------
// 2) exclusive scan of cell histogram (single block, 2048 elements)
// ---------------------------------------------------------------------------
__global__ void __launch_bounds__(256)
scan_kernel() {
    __shared__ int csum[256];
    int t = threadIdx.x;
    int local[8];
    int s = 0;
    #pragma unroll
    for (int k = 0; k < 8; k++) { local[k] = g_hist[t * 8 + k]; s += local[k]; }
    csum[t] = s;
    __syncthreads();
    for (int o = 1; o < 256; o <<= 1) {
        int v = (t >= o) ? csum[t - o] : 0;
        __syncthreads();
        csum[t] += v;
        __syncthreads();
    }
    int run = (t > 0) ? csum[t - 1] : 0;
    #pragma unroll
    for (int k = 0; k < 8; k++) {
        g_cellstart[t * 8 + k] = run;
        g_cellcur[t * 8 + k]   = run;
        run += local[k];
    }
}

// ---------------------------------------------------------------------------
// 3) scatter points into cell-sorted order
// ---------------------------------------------------------------------------
__global__ void __launch_bounds__(256)
scatter_kernel(const float* __restrict__ P, const int* __restrict__ leaf, int BN) {
    int gi = blockIdx.x * blockDim.x + threadIdx.x;
    if (gi >= BN) return;
    int gc  = g_cell[gi];
    int pos = atomicAdd(&g_cellcur[gc], 1);
    float4 v;
    v.x = P[gi * 3 + 0];
    v.y = P[gi * 3 + 1];
    v.z = P[gi * 3 + 2];
    v.w = (leaf[gi] > 0) ? g_enorm[gi] : -1.0f;
    g_spts[pos] = v;
    g_sidx[pos] = gi;
}

// ---------------------------------------------------------------------------
// 4) main: warp per point, 27-cell neighbor scan (9 contiguous x-row ranges)
// ---------------------------------------------------------------------------
__global__ void __launch_bounds__(256)
main_kernel(const float* __restrict__ P, const float* __restrict__ E,
            const int* __restrict__ leaf,
            const float* __restrict__ W1, const float* __restrict__ b1,
            const float* __restrict__ W2, const float* __restrict__ b2,
            float* __restrict__ out, int N, int BN) {
    __shared__ float sW1[64 * 32];
    __shared__ float sW2[32 * 32];
    __shared__ float sb1[32], sb2[32];

    for (int t = threadIdx.x; t < 64 * 32; t += blockDim.x) sW1[t] = W1[t];
    for (int t = threadIdx.x; t < 32 * 32; t += blockDim.x) sW2[t] = W2[t];
    if (threadIdx.x < 32) { sb1[threadIdx.x] = b1[threadIdx.x]; sb2[threadIdx.x] = b2[threadIdx.x]; }
    __syncthreads();

    const int lane = threadIdx.x & 31;
    const int warp = threadIdx.x >> 5;
    const int gi   = blockIdx.x * 8 + warp;
    if (gi >= BN) return;
    const int b = gi >= N ? 1 : 0;

    const float ei       = E[(size_t)gi * 32 + lane];
    const bool  leaf_i   = leaf[gi] > 0;
    const bool  batch_ok = g_leafsum[b] >= 10;
    const bool  active   = leaf_i && batch_ok;

    float outv = ei;

    if (active) {
        const float px = P[gi * 3 + 0];
        const float py = P[gi * 3 + 1];
        const float pz = P[gi * 3 + 2];
        const float pni = px * px + py * py + pz * pz;
        const float eni = g_enorm[gi];

        int c  = (int)g_cell[gi] - b * NC;
        int cx = c % GD, cy = (c / GD) % GD, cz = c / (GD * GD);

        int   cnt_nb = 0, cnt_sim = 0;
        float ssum = 0.0f;

        #pragma unroll
        for (int dz = -1; dz <= 1; dz++) {
            int cz2 = cz + dz;
            if ((unsigned)cz2 >= (unsigned)GD) continue;
            #pragma unroll
            for (int dy = -1; dy <= 1; dy++) {
                int cy2 = cy + dy;
                if ((unsigned)cy2 >= (unsigned)GD) continue;
                int base = b * NC + (cz2 * GD + cy2) * GD;
                int s = g_cellstart[base + max(cx - 1, 0)];
                int e = g_cellstart[base + min(cx + 1, GD - 1) + 1];
                for (int t = s; t < e; t += 32) {
                    int  pos   = t + lane;
                    bool valid = pos < e;
                    float4 v  = valid ? g_spts[pos] : make_float4(1e9f, 1e9f, 1e9f, -1.0f);
                    int    jx = valid ? g_sidx[pos] : 0;
                    float pnj  = v.x * v.x + v.y * v.y + v.z * v.z;
                    float dot3 = px * v.x + py * v.y + pz * v.z;
                    float d2   = pni + pnj - 2.0f * dot3;   // same Gram trick as reference
                    bool cand  = (d2 < R2) && (v.w > 0.0f);
                    unsigned m = __ballot_sync(FULL, cand);
                    cnt_nb += __popc(m);
                    while (m) {
                        int src = __ffs(m) - 1;
                        m &= m - 1;
                        int   j   = __shfl_sync(FULL, jx, src);
                        float enj = __shfl_sync(FULL, v.w, src);
                        float ej  = E[(size_t)j * 32 + lane];
                        float d   = ei * ej;
                        #pragma unroll
                        for (int o = 16; o; o >>= 1) d += __shfl_xor_sync(FULL, d, o);
                        float sim = d / (eni * enj);
                        if (sim > SIM_T) { cnt_sim++; ssum += ej; }   // uniform across warp
                    }
                }
            }
        }

        if (cnt_nb > 1 && cnt_sim > 0) {          // uniform across warp
            float mean = ssum / (float)cnt_sim;
            float h = sb1[lane];
            #pragma unroll
            for (int k = 0; k < 32; k++) {
                float cc = __shfl_sync(FULL, ei, k);
                h = fmaf(cc, sW1[k * 32 + lane], h);
            }
            #pragma unroll
            for (int k = 0; k < 32; k++) {
                float cc = __shfl_sync(FULL, mean, k);
                h = fmaf(cc, sW1[(k + 32) * 32 + lane], h);
            }
            h = fmaxf(h, 0.0f);
            float o = sb2[lane];
            #pragma unroll
            for (int k = 0; k < 32; k++) {
                float hk = __shfl_sync(FULL, h, k);
                o = fmaf(hk, sW2[k * 32 + lane], o);
            }
            outv = o;
        }
    }
    out[(size_t)gi * 32 + lane] = outv;
}

// ---------------------------------------------------------------------------
extern "C" void kernel_launch(void* const* d_in, const int* in_sizes, int n_in,
                              void* d_out, int out_size) {
    const float* P  = (const float*)d_in[0];
    const float* E  = (const float*)d_in[1];
    const int*   L  = (const int*)d_in[2];
    const float* W1 = (const float*)d_in[3];
    const float* b1 = (const float*)d_in[4];
    const float* W2 = (const float*)d_in[5];
    const float* b2 = (const float*)d_in[6];
    float* out = (float*)d_out;

    const int BN = in_sizes[2];   // B*N
    const int B  = 2;
    const int N  = BN / B;

    init_kernel<<<1, 256>>>();
    prep_kernel<<<(BN + 7) / 8, 256>>>(P, E, L, N, BN);
    scan_kernel<<<1, 256>>>();
    scatter_kernel<<<(BN + 255) / 256, 256>>>(P, L, BN);
    main_kernel<<<(BN + 7) / 8, 256>>>(P, E, L, W1, b1, W2, b2, out, N, BN);
}